// round 15
// baseline (speedup 1.0000x reference)
#include <cuda_runtime.h>
#include <cuda_bf16.h>
#include <math.h>
#include <cstdint>

#define Hc 128
#define Wc 128
#define HWc 16384

typedef unsigned long long u64p;

__device__ __forceinline__ u64p pk(float lo, float hi) {
  u64p r; asm("mov.b64 %0, {%1,%2};" : "=l"(r) : "f"(lo), "f"(hi)); return r;
}
__device__ __forceinline__ void fma2(u64p& a, u64p x, u64p y) {
  asm("fma.rn.f32x2 %0, %1, %2, %0;" : "+l"(a) : "l"(x), "l"(y));
}
__device__ __forceinline__ float2 up(u64p v) {
  float2 f; asm("mov.b64 {%0,%1}, %2;" : "=f"(f.x), "=f"(f.y) : "l"(v)); return f;
}
__device__ __forceinline__ uint32_t smem_u32(const void* p) {
  uint32_t a;
  asm("{ .reg .u64 t; cvta.to.shared.u64 t, %1; cvt.u32.u64 %0, t; }" : "=r"(a) : "l"(p));
  return a;
}

// activations scratch
__device__ float g_x1[2*64*HWc];
__device__ float g_f [2*32*HWc];
__device__ float g_zp[2*2*HWc];
__device__ float g_x2[2*64*HWc];
__device__ float g_h [2*32*HWc];
// Prebuilt A fragments (canonical m16n8k16 layout, bf16x2 words):
__device__ uint32_t g_afrag [19*8*32*4];   // final fused GEMM  (K'=304, M=128)
__device__ uint32_t g_afrag1[25*4*32*4];   // conv1   (K'=400, M=64)
__device__ uint32_t g_afrag2[13*2*32*4];   // reduce  (K'=208, M=32)
__device__ uint32_t g_afrag3[18*2*32*4];   // psec3x3 Whi (K'=288, M=32)
__device__ uint32_t g_afrag4[18*2*32*4];   // psec3x3 Wlo

// ---------------------------------------------------------------------------
// common mma helpers
// ---------------------------------------------------------------------------
__device__ __forceinline__ void ldsm2t(uint32_t* r, uint32_t addr) {
  asm volatile("ldmatrix.sync.aligned.m8n8.x2.trans.shared.b16 {%0,%1}, [%2];"
    : "=r"(r[0]), "=r"(r[1]) : "r"(addr));
}
__device__ __forceinline__ void mma_bf16(float* d, const uint32_t* a, const uint32_t* bf) {
  asm volatile(
    "mma.sync.aligned.m16n8k16.row.col.f32.bf16.bf16.f32 "
    "{%0,%1,%2,%3}, {%4,%5,%6,%7}, {%8,%9}, {%0,%1,%2,%3};"
    : "+f"(d[0]), "+f"(d[1]), "+f"(d[2]), "+f"(d[3])
    : "r"(a[0]), "r"(a[1]), "r"(a[2]), "r"(a[3]), "r"(bf[0]), "r"(bf[1]));
}
__device__ __forceinline__ void bf_split(float w, __nv_bfloat16& hi, __nv_bfloat16& lo) {
  hi = __float2bfloat16(w);
  lo = __float2bfloat16(w - __bfloat162float(hi));
}
__device__ __forceinline__ uint32_t pk2bf(__nv_bfloat16 a, __nv_bfloat16 b) {
  return (uint32_t)__bfloat16_as_ushort(a) | ((uint32_t)__bfloat16_as_ushort(b) << 16);
}

// ---------------------------------------------------------------------------
// K-prep: build all A-fragment tables.
// ---------------------------------------------------------------------------
__device__ __forceinline__ __nv_bfloat16 hi_or_lo(float v, bool lo) {
  __nv_bfloat16 hi = __float2bfloat16(v);
  if (!lo) return hi;
  return __float2bfloat16(v - __bfloat162float(hi));
}
__device__ __forceinline__ __nv_bfloat16 aval_fin(int m, int k,
    const float* w2, const float* b2, const float* wp2, const float* bp2)
{
  if      (k < 64)  return hi_or_lo(w2[m*64 + k], false);
  else if (k < 128) return hi_or_lo(w2[m*64 + k - 64], true);
  else if (k < 192) return hi_or_lo(w2[m*64 + k - 128], false);
  else if (k < 224) return hi_or_lo(wp2[m*32 + k - 192], false);
  else if (k < 256) return hi_or_lo(wp2[m*32 + k - 224], true);
  else if (k < 288) return hi_or_lo(wp2[m*32 + k - 256], false);
  else if (k == 288) return hi_or_lo(b2[m], false);
  else if (k == 289) return hi_or_lo(b2[m], true);
  else if (k == 290) return hi_or_lo(b2[m], false);
  else if (k == 291) return hi_or_lo(bp2[m], false);
  else if (k == 292) return hi_or_lo(bp2[m], true);
  return __float2bfloat16(0.f);
}
__device__ __forceinline__ __nv_bfloat16 aval_c1(int m, int k,
    const float* w1, const float* b1)
{
  if      (k < 128) return hi_or_lo(w1[m*128 + k], false);
  else if (k < 256) return hi_or_lo(w1[m*128 + k - 128], true);
  else if (k < 384) return hi_or_lo(w1[m*128 + k - 256], false);
  else if (k == 384) return hi_or_lo(b1[m], false);
  else if (k == 385) return hi_or_lo(b1[m], true);
  return __float2bfloat16(0.f);
}
__device__ __forceinline__ __nv_bfloat16 aval_rd(int m, int k,
    const float* wr, const float* br)
{
  if      (k < 64)  return hi_or_lo(wr[m*64 + k], false);
  else if (k < 128) return hi_or_lo(wr[m*64 + k - 64], true);
  else if (k < 192) return hi_or_lo(wr[m*64 + k - 128], false);
  else if (k == 192) return hi_or_lo(br[m], false);
  else if (k == 193) return hi_or_lo(br[m], true);
  return __float2bfloat16(0.f);
}
// psec 3x3: k = dj*96 + di*32 + ci  ->  wp1[m][ci][di][dj]
__device__ __forceinline__ __nv_bfloat16 aval_ps(int m, int k,
    const float* wp1, bool lo)
{
  int dj = k / 96, rem = k - dj*96;
  int di = rem >> 5, ci = rem & 31;
  return hi_or_lo(wp1[m*288 + ci*9 + di*3 + dj], lo);
}

__global__ void k_prep_afrag(
    const float* __restrict__ w2,  const float* __restrict__ b2,
    const float* __restrict__ wp2, const float* __restrict__ bp2,
    const float* __restrict__ w1,  const float* __restrict__ b1,
    const float* __restrict__ wr,  const float* __restrict__ br,
    const float* __restrict__ wp1)
{
  int idx = blockIdx.x*256 + threadIdx.x;
  if (idx < 19456) {
    int q = idx & 3, lane = (idx >> 2) & 31, mt = (idx >> 7) & 7, kt = idx >> 10;
    int m = mt*16 + (lane >> 2) + ((q & 1) << 3);
    int c = kt*16 + ((lane & 3) << 1) + ((q >> 1) << 3);
    g_afrag[idx] = pk2bf(aval_fin(m, c, w2, b2, wp2, bp2),
                         aval_fin(m, c+1, w2, b2, wp2, bp2));
    return;
  }
  idx -= 19456;
  if (idx < 12800) {
    int q = idx & 3, lane = (idx >> 2) & 31, mt = (idx >> 7) & 3, kt = idx >> 9;
    int m = mt*16 + (lane >> 2) + ((q & 1) << 3);
    int c = kt*16 + ((lane & 3) << 1) + ((q >> 1) << 3);
    g_afrag1[idx] = pk2bf(aval_c1(m, c, w1, b1), aval_c1(m, c+1, w1, b1));
    return;
  }
  idx -= 12800;
  if (idx < 3328) {
    int q = idx & 3, lane = (idx >> 2) & 31, mt = (idx >> 7) & 1, kt = idx >> 8;
    int m = mt*16 + (lane >> 2) + ((q & 1) << 3);
    int c = kt*16 + ((lane & 3) << 1) + ((q >> 1) << 3);
    g_afrag2[idx] = pk2bf(aval_rd(m, c, wr, br), aval_rd(m, c+1, wr, br));
    return;
  }
  idx -= 3328;
  if (idx < 4608) {
    int q = idx & 3, lane = (idx >> 2) & 31, mt = (idx >> 7) & 1, kt = idx >> 8;
    int m = mt*16 + (lane >> 2) + ((q & 1) << 3);
    int c = kt*16 + ((lane & 3) << 1) + ((q >> 1) << 3);
    g_afrag3[idx] = pk2bf(aval_ps(m, c, wp1, false), aval_ps(m, c+1, wp1, false));
    return;
  }
  idx -= 4608;
  if (idx < 4608) {
    int q = idx & 3, lane = (idx >> 2) & 31, mt = (idx >> 7) & 1, kt = idx >> 8;
    int m = mt*16 + (lane >> 2) + ((q & 1) << 3);
    int c = kt*16 + ((lane & 3) << 1) + ((q >> 1) << 3);
    g_afrag4[idx] = pk2bf(aval_ps(m, c, wp1, true), aval_ps(m, c+1, wp1, true));
  }
}

// ---------------------------------------------------------------------------
// K1 (HMMA, R11 passing version): half-row (64 px).
// ---------------------------------------------------------------------------
#define PB1 72
#define FS_OFF 0
#define B1F_OFF 8704
#define SMF_BYTES 66304

__global__ __launch_bounds__(256, 3) void k_front_mma(
    const float* __restrict__ x, const float* __restrict__ a1p,
    float* __restrict__ dummy)
{
  extern __shared__ char smf[];
  const int t = threadIdx.x;
  const int wid = t >> 5, lane = t & 31;
  const int h  = blockIdx.x;
  const int p0 = blockIdx.y * 64;
  const int b  = blockIdx.z;
  const float a1 = *a1p;
  float* fs = (float*)(smf + FS_OFF);
  __nv_bfloat16* B = (__nv_bfloat16*)(smf + B1F_OFF);
  const uint32_t Bbase = smem_u32(smf) + B1F_OFF;

  {
    const float* xb = x + (b*128)*HWc + h*Wc + p0;
    for (int i = t; i < 4096; i += 256) {
      int c = i >> 5, n2 = (i & 31) * 2;
      float2 xv = *(const float2*)&xb[c*HWc + n2];
      __nv_bfloat16 h0, l0, h1, l1; bf_split(xv.x, h0, l0); bf_split(xv.y, h1, l1);
      uint32_t hh = pk2bf(h0, h1), ll = pk2bf(l0, l1);
      *(uint32_t*)&B[c*PB1 + n2]         = hh;
      *(uint32_t*)&B[(128 + c)*PB1 + n2] = hh;
      *(uint32_t*)&B[(256 + c)*PB1 + n2] = ll;
    }
    __nv_bfloat16 one = __float2bfloat16(1.0f);
    uint32_t oo = pk2bf(one, one);
    for (int i = t; i < 512; i += 256) {
      int r = 384 + (i >> 5), n2 = (i & 31) * 2;
      *(uint32_t*)&B[r*PB1 + n2] = (r < 386) ? oo : 0u;
    }
  }
  __syncthreads();

  const int mw = wid & 3, nw = wid >> 2;
  const uint4* __restrict__ afp1 = (const uint4*)g_afrag1;
  float d[4][4];
  #pragma unroll
  for (int nt = 0; nt < 4; nt++)
    #pragma unroll
    for (int q = 0; q < 4; q++) d[nt][q] = 0.f;

  uint4 a0 = afp1[(0*4 + mw)*32 + lane];
  #pragma unroll 1
  for (int kt = 0; kt < 25; kt++) {
    uint4 na;
    if (kt < 24) na = afp1[((kt+1)*4 + mw)*32 + lane];
    const uint32_t brow = Bbase + (uint32_t)(((kt*16 + (lane & 15))*PB1 + nw*32) * 2);
    #pragma unroll
    for (int nt = 0; nt < 4; nt++) {
      uint32_t bf[2];
      ldsm2t(bf, brow + nt*16);
      mma_bf16(d[nt], (const uint32_t*)&a0, bf);
    }
    a0 = na;
  }
  __syncthreads();

  {
    const int r = lane >> 2, c2 = (lane & 3) * 2;
    float* gx1b = g_x1 + (b*64)*HWc + h*Wc + p0;
    #pragma unroll
    for (int nt = 0; nt < 4; nt++) {
      const int n = nw*32 + nt*8 + c2;
      #pragma unroll
      for (int half = 0; half < 2; half++) {
        const int m = mw*16 + r + half*8;
        float v0 = d[nt][half*2], v1 = d[nt][half*2 + 1];
        v0 = (v0 >= 0.f) ? v0 : a1*v0;
        v1 = (v1 >= 0.f) ? v1 : a1*v1;
        *(float2*)&gx1b[m*HWc + n] = make_float2(v0, v1);
        __nv_bfloat16 h0, l0, h1, l1; bf_split(v0, h0, l0); bf_split(v1, h1, l1);
        uint32_t hh = pk2bf(h0, h1), ll = pk2bf(l0, l1);
        *(uint32_t*)&B[m*PB1 + n]         = hh;
        *(uint32_t*)&B[(64 + m)*PB1 + n]  = hh;
        *(uint32_t*)&B[(128 + m)*PB1 + n] = ll;
      }
    }
    __nv_bfloat16 one = __float2bfloat16(1.0f);
    uint32_t oo = pk2bf(one, one);
    for (int i = t; i < 512; i += 256) {
      int rr = 192 + (i >> 5), n2 = (i & 31) * 2;
      *(uint32_t*)&B[rr*PB1 + n2] = (rr < 194) ? oo : 0u;
    }
  }
  __syncthreads();

  const int mw2 = wid & 1, nw2 = wid >> 1;
  const uint4* __restrict__ afp2 = (const uint4*)g_afrag2;
  float d2[2][4];
  #pragma unroll
  for (int nt = 0; nt < 2; nt++)
    #pragma unroll
    for (int q = 0; q < 4; q++) d2[nt][q] = 0.f;

  uint4 a2 = afp2[(0*2 + mw2)*32 + lane];
  #pragma unroll 1
  for (int kt = 0; kt < 13; kt++) {
    uint4 na;
    if (kt < 12) na = afp2[((kt+1)*2 + mw2)*32 + lane];
    const uint32_t brow = Bbase + (uint32_t)(((kt*16 + (lane & 15))*PB1 + nw2*16) * 2);
    #pragma unroll
    for (int nt = 0; nt < 2; nt++) {
      uint32_t bf[2];
      ldsm2t(bf, brow + nt*16);
      mma_bf16(d2[nt], (const uint32_t*)&a2, bf);
    }
    a2 = na;
  }

  {
    const int r = lane >> 2, c2 = (lane & 3) * 2;
    float* gfb = g_f + (b*32)*HWc + h*Wc + p0;
    #pragma unroll
    for (int nt = 0; nt < 2; nt++) {
      const int n = nw2*16 + nt*8 + c2;
      #pragma unroll
      for (int half = 0; half < 2; half++) {
        const int m = mw2*16 + r + half*8;
        float v0 = fmaxf(d2[nt][half*2], 0.f);
        float v1 = fmaxf(d2[nt][half*2 + 1], 0.f);
        *(float2*)&gfb[m*HWc + n] = make_float2(v0, v1);
        *(float2*)&fs[m*68 + n]   = make_float2(v0, v1);
      }
    }
  }
  __syncthreads();

  if (t < 64) {
    float mx = -1e30f, sum = 0.f;
    #pragma unroll
    for (int c = 0; c < 32; c++) {
      float v = fs[c*68 + t];
      mx = fmaxf(mx, v);
      sum += v;
    }
    g_zp[(b*2)*HWc + h*Wc + p0 + t]   = mx;
    g_zp[(b*2+1)*HWc + h*Wc + p0 + t] = sum * (1.f/32.f);
  }
}

// ---------------------------------------------------------------------------
// K2: involution, ch-paired x1 layout (R12/R13 passing version). Tile 32x2.
// ---------------------------------------------------------------------------
__global__ __launch_bounds__(256, 2) void k_inv(
    const float* __restrict__ ws, const float* __restrict__ bs,
    const float* __restrict__ a2p)
{
  extern __shared__ float sm[];
  float* x1h = sm;                // 32 chp * 304 pix * 2 = 19456
  float* wss = x1h + 19456;       // 6272
  float* bss = wss + 6272;        // 196
  float* fts = bss + 196;         // 64*33
  const int t = threadIdx.x;
  const int w0 = blockIdx.x << 5;
  const int h0 = blockIdx.y << 1;
  const int b  = blockIdx.z;
  const float a2 = *a2p;

  const float* gx1b = g_x1 + (b*64)*HWc;
  for (int i = t; i < 19456; i += 256) {
    int ch = i / 304, r = i - ch*304;
    int yy = r / 38, xx = r - yy*38;
    int gh = h0 - 3 + yy, gw = w0 - 3 + xx;
    float v = 0.f;
    if ((unsigned)gh < 128u && (unsigned)gw < 128u)
      v = gx1b[ch*HWc + gh*Wc + gw];
    x1h[(ch >> 1)*608 + r*2 + (ch & 1)] = v;
  }
  for (int i = t; i < 6272; i += 256) wss[i] = ws[i];
  if (t < 196) bss[t] = bs[t];
  const float* gfb = g_f + (b*32)*HWc;
  for (int i = t; i < 2048; i += 256) {
    int c = i >> 6, p = i & 63;
    fts[p*33 + c] = gfb[c*HWc + (h0 + (p>>5))*Wc + w0 + (p&31)];
  }
  __syncthreads();

  const int p = t & 63, j = t >> 6;
  const int py = p >> 5, px = p & 31;

  u64p fp[16];
  #pragma unroll
  for (int c2 = 0; c2 < 16; c2++)
    fp[c2] = pk(fts[p*33 + 2*c2], fts[p*33 + 2*c2 + 1]);

  u64p acc2[8];
  #pragma unroll
  for (int chp = 0; chp < 8; chp++) acc2[chp] = 0ull;

  const float* wb = wss + j*49*32;
  const float* bb = bss + j*49;
  const float* xb = x1h + (j*8)*608 + (py*38 + px)*2;

  #pragma unroll 1
  for (int dy = 0; dy < 7; dy++) {
    #pragma unroll 1
    for (int dx = 0; dx < 7; dx++) {
      const int tt = dy*7 + dx;
      const float* wr2 = wb + tt*32;
      u64p k0 = 0ull, k1 = 0ull;
      #pragma unroll
      for (int c4 = 0; c4 < 8; c4++) {
        float4 wv = *(const float4*)&wr2[c4*4];
        fma2(k0, pk(wv.x, wv.y), fp[2*c4]);
        fma2(k1, pk(wv.z, wv.w), fp[2*c4 + 1]);
      }
      float2 ka = up(k0), kb = up(k1);
      const float kwt = bb[tt] + ((ka.x + ka.y) + (kb.x + kb.y));
      const u64p kd = pk(kwt, kwt);
      const float* src = xb + (dy*38 + dx)*2;
      #pragma unroll
      for (int chp = 0; chp < 8; chp++) {
        u64p v = *(const u64p*)&src[chp*608];
        fma2(acc2[chp], kd, v);
      }
    }
  }

  float* gx2b = g_x2 + (b*64 + j*16)*HWc + (h0 + py)*Wc + (w0 + px);
  #pragma unroll
  for (int chp = 0; chp < 8; chp++) {
    float2 v = up(acc2[chp]);
    float e = (v.x >= 0.f) ? v.x : a2*v.x;
    float o = (v.y >= 0.f) ? v.y : a2*v.y;
    gx2b[(2*chp)*HWc]     = e;
    gx2b[(2*chp + 1)*HWc] = o;
  }
}

// ---------------------------------------------------------------------------
// K3 (NEW, HMMA): psec 3x3 conv as im2col GEMM.
// CTA = one image row (128 px). D[32 oc][128 px], K'=288 (dj,di,ci).
// 3 accumulating passes: Whi*xhi, Wlo*xhi, Whi*xlo — 2 B builds.
// ---------------------------------------------------------------------------
#define PBP 136
#define SMP_BYTES (288*PBP*2)   // 78336

__global__ __launch_bounds__(256, 2) void k_psec_mma(
    const float* __restrict__ bp1, const float* __restrict__ app)
{
  extern __shared__ char smp[];
  __nv_bfloat16* B = (__nv_bfloat16*)smp;
  const uint32_t Bbase = smem_u32(smp);
  const int t = threadIdx.x;
  const int wid = t >> 5, lane = t & 31;
  const int h = blockIdx.x;
  const int b = blockIdx.y;
  const float ap = *app;
  const float* gfb = g_f + (b*32)*HWc;

  const int mw = wid & 1;        // 2 m-tiles (32 oc)
  const int nw = wid >> 1;       // 4 n-quarters (32 px each)

  float d[4][4];
  #pragma unroll
  for (int nt = 0; nt < 4; nt++)
    #pragma unroll
    for (int q = 0; q < 4; q++) d[nt][q] = 0.f;

  // ---- build B = xhi ----
  for (int i = t; i < 288*64; i += 256) {
    int r = i >> 6, n2 = (i & 63) * 2;
    int dj = r / 96, rem = r - dj*96;
    int di = rem >> 5, ci = rem & 31;
    int gh = h + di - 1;
    float v0 = 0.f, v1 = 0.f;
    if ((unsigned)gh < 128u) {
      const float* fr = gfb + ci*HWc + gh*Wc;
      int c0 = n2 + dj - 1;
      if ((unsigned)c0 < 128u) v0 = fr[c0];
      if ((unsigned)(c0+1) < 128u) v1 = fr[c0+1];
    }
    *(uint32_t*)&B[r*PBP + n2] = pk2bf(__float2bfloat16(v0), __float2bfloat16(v1));
  }
  __syncthreads();

  // pass 1: Whi * xhi ; pass 2: Wlo * xhi
  #pragma unroll 1
  for (int pass = 0; pass < 2; pass++) {
    const uint4* __restrict__ afp = (const uint4*)(pass == 0 ? g_afrag3 : g_afrag4);
    uint4 a0 = afp[(0*2 + mw)*32 + lane];
    #pragma unroll 1
    for (int kt = 0; kt < 18; kt++) {
      uint4 na;
      if (kt < 17) na = afp[((kt+1)*2 + mw)*32 + lane];
      const uint32_t brow = Bbase + (uint32_t)(((kt*16 + (lane & 15))*PBP + nw*32) * 2);
      #pragma unroll
      for (int nt = 0; nt < 4; nt++) {
        uint32_t bf[2];
        ldsm2t(bf, brow + nt*16);
        mma_bf16(d[nt], (const uint32_t*)&a0, bf);
      }
      a0 = na;
    }
  }
  __syncthreads();

  // ---- build B = xlo ----
  for (int i = t; i < 288*64; i += 256) {
    int r = i >> 6, n2 = (i & 63) * 2;
    int dj = r / 96, rem = r - dj*96;
    int di = rem >> 5, ci = rem & 31;
    int gh = h + di - 1;
    float v0 = 0.f, v1 = 0.f;
    if ((unsigned)gh < 128u) {
      const float* fr = gfb + ci*HWc + gh*Wc;
      int c0 = n2 + dj - 1;
      if ((unsigned)c0 < 128u) v0 = fr[c0];
      if ((unsigned)(c0+1) < 128u) v1 = fr[c0+1];
    }
    __nv_bfloat16 h0, l0, h1, l1; bf_split(v0, h0, l0); bf_split(v1, h1, l1);
    *(uint32_t*)&B[r*PBP + n2] = pk2bf(l0, l1);
  }
  __syncthreads();

  // pass 3: Whi * xlo
  {
    const uint4* __restrict__ afp = (const uint4*)g_afrag3;
    uint4 a0 = afp[(0*2 + mw)*32 + lane];
    #pragma unroll 1
    for (int kt = 0; kt < 18; kt++) {
      uint4 na;
      if (kt < 17) na = afp[((kt+1)*2 + mw)*32 + lane];
      const uint32_t brow = Bbase + (uint32_t)(((kt*16 + (lane & 15))*PBP + nw*32) * 2);
      #pragma unroll
      for (int nt = 0; nt < 4; nt++) {
        uint32_t bf[2];
        ldsm2t(bf, brow + nt*16);
        mma_bf16(d[nt], (const uint32_t*)&a0, bf);
      }
      a0 = na;
    }
  }

  // ---- epilogue: +bias, PReLU -> g_h ----
  {
    const int r = lane >> 2, c2 = (lane & 3) * 2;
    float* ghb = g_h + (b*32)*HWc + h*Wc;
    #pragma unroll
    for (int half = 0; half < 2; half++) {
      const int m = mw*16 + r + half*8;
      const float bv = bp1[m];
      #pragma unroll
      for (int nt = 0; nt < 4; nt++) {
        const int n = nw*32 + nt*8 + c2;
        float v0 = d[nt][half*2]     + bv;
        float v1 = d[nt][half*2 + 1] + bv;
        v0 = (v0 >= 0.f) ? v0 : ap*v0;
        v1 = (v1 >= 0.f) ? v1 : ap*v1;
        *(float2*)&ghb[m*HWc + n] = make_float2(v0, v1);
      }
    }
  }
}

// ---------------------------------------------------------------------------
// K4: HMMA final (R10/R11 passing version).
// ---------------------------------------------------------------------------
#define PB 136
#define B_OFF 8448
#define SM4_BYTES (B_OFF + 304*PB*2)   // 91136

__global__ __launch_bounds__(256, 2) void k_final_mma(
    const float* __restrict__ wa, const float* __restrict__ ba,
    float* __restrict__ out)
{
  extern __shared__ char sm4[];
  const int t = threadIdx.x;
  const int wid = t >> 5, lane = t & 31;
  const int h = blockIdx.x & 127;
  const int b = blockIdx.x >> 7;
  float* attns = (float*)(sm4);
  float* was   = (float*)(sm4 + 512);
  float* zph   = (float*)(sm4 + 912);
  __nv_bfloat16* B = (__nv_bfloat16*)(sm4 + B_OFF);
  const uint32_t sbase = smem_u32(sm4);

  {
    const float* gzb = g_zp + (b*2)*HWc;
    for (int i = t; i < 1876; i += 256) {
      int c = i / 938, r = i - c*938;
      int yy = r / 134, xx = r - yy*134;
      int gh = h - 3 + yy, gw = xx - 3;
      float v = 0.f;
      if ((unsigned)gh < 128u && (unsigned)gw < 128u)
        v = gzb[c*HWc + gh*Wc + gw];
      zph[i] = v;
    }
    if (t < 98) was[t] = wa[t];
  }
  __syncthreads();

  if (t < 128) {
    float aacc = *ba;
    #pragma unroll
    for (int dy = 0; dy < 7; dy++)
      #pragma unroll
      for (int dx = 0; dx < 7; dx++) {
        const int o1 = dy*134 + t + dx;
        aacc += was[dy*7+dx]*zph[o1] + was[49 + dy*7+dx]*zph[938 + o1];
      }
    attns[t] = 1.f / (1.f + expf(-aacc));
  }
  __syncthreads();

  {
    const float* gx2b = g_x2 + (b*64)*HWc + h*Wc;
    for (int i = t; i < 4096; i += 256) {
      int c = i >> 6, n2 = (i & 63) * 2;
      float2 xv = *(const float2*)&gx2b[c*HWc + n2];
      float y0 = xv.x * attns[n2], y1 = xv.y * attns[n2+1];
      __nv_bfloat16 h0, l0, h1, l1; bf_split(y0, h0, l0); bf_split(y1, h1, l1);
      uint32_t hh = pk2bf(h0, h1), ll = pk2bf(l0, l1);
      *(uint32_t*)&B[c*PB + n2]         = hh;
      *(uint32_t*)&B[(64 + c)*PB + n2]  = hh;
      *(uint32_t*)&B[(128 + c)*PB + n2] = ll;
    }
    const float* ghb = g_h + (b*32)*HWc + h*Wc;
    for (int i = t; i < 2048; i += 256) {
      int c = i >> 6, n2 = (i & 63) * 2;
      float2 hv = *(const float2*)&ghb[c*HWc + n2];
      __nv_bfloat16 h0, l0, h1, l1; bf_split(hv.x, h0, l0); bf_split(hv.y, h1, l1);
      uint32_t hh = pk2bf(h0, h1), ll = pk2bf(l0, l1);
      *(uint32_t*)&B[(192 + c)*PB + n2] = hh;
      *(uint32_t*)&B[(224 + c)*PB + n2] = hh;
      *(uint32_t*)&B[(256 + c)*PB + n2] = ll;
    }
    if (t < 64) {
      int n2 = t*2;
      __nv_bfloat16 h0, l0, h1, l1;
      bf_split(attns[n2], h0, l0); bf_split(attns[n2+1], h1, l1);
      uint32_t hh = pk2bf(h0, h1), ll = pk2bf(l0, l1);
      *(uint32_t*)&B[288*PB + n2] = hh;
      *(uint32_t*)&B[289*PB + n2] = hh;
      *(uint32_t*)&B[290*PB + n2] = ll;
      __nv_bfloat16 one = __float2bfloat16(1.0f);
      uint32_t oo = pk2bf(one, one);
      *(uint32_t*)&B[291*PB + n2] = oo;
      *(uint32_t*)&B[292*PB + n2] = oo;
    }
    for (int i = t; i < 11*64; i += 256) {
      int r = 293 + (i >> 6), n2 = (i & 63) * 2;
      *(uint32_t*)&B[r*PB + n2] = 0u;
    }
  }
  __syncthreads();

  const int mw = wid & 3, nw = wid >> 2;
  const uint32_t Bbase = sbase + B_OFF;
  const uint4* __restrict__ afp = (const uint4*)g_afrag;

  float d[2][8][4];
  #pragma unroll
  for (int mt = 0; mt < 2; mt++)
    #pragma unroll
    for (int nt = 0; nt < 8; nt++)
      #pragma unroll
      for (int q = 0; q < 4; q++) d[mt][nt][q] = 0.f;

  uint4 a0 = afp[(0*8 + mw*2 + 0)*32 + lane];
  uint4 a1 = afp[(0*8 + mw*2 + 1)*32 + lane];

  #pragma unroll 1
  for (int kt = 0; kt < 19; kt++) {
    uint4 na0, na1;
    if (kt < 18) {
      na0 = afp[((kt+1)*8 + mw*2 + 0)*32 + lane];
      na1 = afp[((kt+1)*8 + mw*2 + 1)*32 + lane];
    }
    const uint32_t brow = Bbase + (uint32_t)(((kt*16 + (lane & 15))*PB + nw*64) * 2);
    #pragma unroll
    for (int nt = 0; nt < 8; nt++) {
      uint32_t bf[2];
      ldsm2t(bf, brow + nt*16);
      mma_bf16(d[0][nt], (const uint32_t*)&a0, bf);
      mma_bf16(d[1][nt], (const uint32_t*)&a1, bf);
    }
    a0 = na0; a1 = na1;
  }

  const int r = lane >> 2, c2 = (lane & 3) * 2;
  const int m_base = mw*32, n_base = nw*64;
  float* ob = out + (b*128)*HWc + h*Wc;
  #pragma unroll
  for (int mt = 0; mt < 2; mt++) {
    #pragma unroll
    for (int nt = 0; nt < 8; nt++) {
      const int m = m_base + mt*16 + r;
      const int n = n_base + nt*8 + c2;
      *(float2*)&ob[m*HWc + n]       = make_float2(d[mt][nt][0], d[mt][nt][1]);
      *(float2*)&ob[(m + 8)*HWc + n] = make_float2(d[mt][nt][2], d[mt][nt][3]);
    }
  }
}

// ---------------------------------------------------------------------------
extern "C" void kernel_launch(void* const* d_in, const int* in_sizes, int n_in,
                              void* d_out, int out_size)
{
  const float* x   = (const float*)d_in[0];
  const float* w1  = (const float*)d_in[1];
  const float* b1  = (const float*)d_in[2];
  const float* a1  = (const float*)d_in[3];
  const float* wr  = (const float*)d_in[4];
  const float* br  = (const float*)d_in[5];
  const float* ws  = (const float*)d_in[6];
  const float* bs  = (const float*)d_in[7];
  const float* a2  = (const float*)d_in[8];
  const float* w2  = (const float*)d_in[9];
  const float* b2  = (const float*)d_in[10];
  const float* wa  = (const float*)d_in[11];
  const float* ba  = (const float*)d_in[12];
  const float* wp1 = (const float*)d_in[13];
  const float* bp1 = (const float*)d_in[14];
  const float* ap  = (const float*)d_in[15];
  const float* wp2 = (const float*)d_in[16];
  const float* bp2 = (const float*)d_in[17];
  float* out = (float*)d_out;

  const int s2 = 28036 * 4;   // k_inv

  cudaFuncSetAttribute(k_front_mma, cudaFuncAttributeMaxDynamicSharedMemorySize, SMF_BYTES);
  cudaFuncSetAttribute(k_inv,       cudaFuncAttributeMaxDynamicSharedMemorySize, s2);
  cudaFuncSetAttribute(k_psec_mma,  cudaFuncAttributeMaxDynamicSharedMemorySize, SMP_BYTES);
  cudaFuncSetAttribute(k_final_mma, cudaFuncAttributeMaxDynamicSharedMemorySize, SM4_BYTES);

  k_prep_afrag<<<175, 256>>>(w2, b2, wp2, bp2, w1, b1, wr, br, wp1);
  k_front_mma<<<dim3(128, 2, 2), 256, SMF_BYTES>>>(x, a1, out);
  k_inv  <<<dim3(4, 64, 2), 256, s2>>>(ws, bs, a2);
  k_psec_mma<<<dim3(128, 2), 256, SMP_BYTES>>>(bp1, ap);
  k_final_mma<<<256, 256, SM4_BYTES>>>(wa, ba, out);
}

// round 17
// speedup vs baseline: 1.2283x; 1.2283x over previous
#include <cuda_runtime.h>
#include <cuda_bf16.h>
#include <math.h>
#include <cstdint>

#define Hc 128
#define Wc 128
#define HWc 16384

typedef unsigned long long u64p;

__device__ __forceinline__ u64p pk(float lo, float hi) {
  u64p r; asm("mov.b64 %0, {%1,%2};" : "=l"(r) : "f"(lo), "f"(hi)); return r;
}
__device__ __forceinline__ void fma2(u64p& a, u64p x, u64p y) {
  asm("fma.rn.f32x2 %0, %1, %2, %0;" : "+l"(a) : "l"(x), "l"(y));
}
__device__ __forceinline__ float2 up(u64p v) {
  float2 f; asm("mov.b64 {%0,%1}, %2;" : "=f"(f.x), "=f"(f.y) : "l"(v)); return f;
}
__device__ __forceinline__ uint32_t smem_u32(const void* p) {
  uint32_t a;
  asm("{ .reg .u64 t; cvta.to.shared.u64 t, %1; cvt.u32.u64 %0, t; }" : "=r"(a) : "l"(p));
  return a;
}

// activations scratch
__device__ float g_x1[2*64*HWc];
__device__ float g_f [2*32*HWc];
__device__ float g_zp[2*2*HWc];
__device__ float g_x2[2*64*HWc];
__device__ float g_h [2*32*HWc];
// Prebuilt A fragments (canonical m16n8k16 layout, bf16x2 words):
__device__ uint32_t g_afrag [19*8*32*4];   // final fused GEMM  (K'=304, M=128)
__device__ uint32_t g_afrag1[25*4*32*4];   // conv1   (K'=400, M=64)
__device__ uint32_t g_afrag2[13*2*32*4];   // reduce  (K'=208, M=32)
__device__ uint32_t g_afrag3[18*2*32*4];   // psec3x3 Whi (K'=288, M=32)
__device__ uint32_t g_afrag4[18*2*32*4];   // psec3x3 Wlo

// ---------------------------------------------------------------------------
// common mma helpers
// ---------------------------------------------------------------------------
__device__ __forceinline__ void ldsm2t(uint32_t* r, uint32_t addr) {
  asm volatile("ldmatrix.sync.aligned.m8n8.x2.trans.shared.b16 {%0,%1}, [%2];"
    : "=r"(r[0]), "=r"(r[1]) : "r"(addr));
}
__device__ __forceinline__ void mma_bf16(float* d, const uint32_t* a, const uint32_t* bf) {
  asm volatile(
    "mma.sync.aligned.m16n8k16.row.col.f32.bf16.bf16.f32 "
    "{%0,%1,%2,%3}, {%4,%5,%6,%7}, {%8,%9}, {%0,%1,%2,%3};"
    : "+f"(d[0]), "+f"(d[1]), "+f"(d[2]), "+f"(d[3])
    : "r"(a[0]), "r"(a[1]), "r"(a[2]), "r"(a[3]), "r"(bf[0]), "r"(bf[1]));
}
__device__ __forceinline__ void bf_split(float w, __nv_bfloat16& hi, __nv_bfloat16& lo) {
  hi = __float2bfloat16(w);
  lo = __float2bfloat16(w - __bfloat162float(hi));
}
__device__ __forceinline__ uint32_t pk2bf(__nv_bfloat16 a, __nv_bfloat16 b) {
  return (uint32_t)__bfloat16_as_ushort(a) | ((uint32_t)__bfloat16_as_ushort(b) << 16);
}

// ---------------------------------------------------------------------------
// K-prep: build all A-fragment tables.
// ---------------------------------------------------------------------------
__device__ __forceinline__ __nv_bfloat16 hi_or_lo(float v, bool lo) {
  __nv_bfloat16 hi = __float2bfloat16(v);
  if (!lo) return hi;
  return __float2bfloat16(v - __bfloat162float(hi));
}
__device__ __forceinline__ __nv_bfloat16 aval_fin(int m, int k,
    const float* w2, const float* b2, const float* wp2, const float* bp2)
{
  if      (k < 64)  return hi_or_lo(w2[m*64 + k], false);
  else if (k < 128) return hi_or_lo(w2[m*64 + k - 64], true);
  else if (k < 192) return hi_or_lo(w2[m*64 + k - 128], false);
  else if (k < 224) return hi_or_lo(wp2[m*32 + k - 192], false);
  else if (k < 256) return hi_or_lo(wp2[m*32 + k - 224], true);
  else if (k < 288) return hi_or_lo(wp2[m*32 + k - 256], false);
  else if (k == 288) return hi_or_lo(b2[m], false);
  else if (k == 289) return hi_or_lo(b2[m], true);
  else if (k == 290) return hi_or_lo(b2[m], false);
  else if (k == 291) return hi_or_lo(bp2[m], false);
  else if (k == 292) return hi_or_lo(bp2[m], true);
  return __float2bfloat16(0.f);
}
__device__ __forceinline__ __nv_bfloat16 aval_c1(int m, int k,
    const float* w1, const float* b1)
{
  if      (k < 128) return hi_or_lo(w1[m*128 + k], false);
  else if (k < 256) return hi_or_lo(w1[m*128 + k - 128], true);
  else if (k < 384) return hi_or_lo(w1[m*128 + k - 256], false);
  else if (k == 384) return hi_or_lo(b1[m], false);
  else if (k == 385) return hi_or_lo(b1[m], true);
  return __float2bfloat16(0.f);
}
__device__ __forceinline__ __nv_bfloat16 aval_rd(int m, int k,
    const float* wr, const float* br)
{
  if      (k < 64)  return hi_or_lo(wr[m*64 + k], false);
  else if (k < 128) return hi_or_lo(wr[m*64 + k - 64], true);
  else if (k < 192) return hi_or_lo(wr[m*64 + k - 128], false);
  else if (k == 192) return hi_or_lo(br[m], false);
  else if (k == 193) return hi_or_lo(br[m], true);
  return __float2bfloat16(0.f);
}
// psec 3x3: k = dj*96 + di*32 + ci  ->  wp1[m][ci][di][dj]
__device__ __forceinline__ __nv_bfloat16 aval_ps(int m, int k,
    const float* wp1, bool lo)
{
  int dj = k / 96, rem = k - dj*96;
  int di = rem >> 5, ci = rem & 31;
  return hi_or_lo(wp1[m*288 + ci*9 + di*3 + dj], lo);
}

__global__ void k_prep_afrag(
    const float* __restrict__ w2,  const float* __restrict__ b2,
    const float* __restrict__ wp2, const float* __restrict__ bp2,
    const float* __restrict__ w1,  const float* __restrict__ b1,
    const float* __restrict__ wr,  const float* __restrict__ br,
    const float* __restrict__ wp1)
{
  int idx = blockIdx.x*256 + threadIdx.x;
  if (idx < 19456) {
    int q = idx & 3, lane = (idx >> 2) & 31, mt = (idx >> 7) & 7, kt = idx >> 10;
    int m = mt*16 + (lane >> 2) + ((q & 1) << 3);
    int c = kt*16 + ((lane & 3) << 1) + ((q >> 1) << 3);
    g_afrag[idx] = pk2bf(aval_fin(m, c, w2, b2, wp2, bp2),
                         aval_fin(m, c+1, w2, b2, wp2, bp2));
    return;
  }
  idx -= 19456;
  if (idx < 12800) {
    int q = idx & 3, lane = (idx >> 2) & 31, mt = (idx >> 7) & 3, kt = idx >> 9;
    int m = mt*16 + (lane >> 2) + ((q & 1) << 3);
    int c = kt*16 + ((lane & 3) << 1) + ((q >> 1) << 3);
    g_afrag1[idx] = pk2bf(aval_c1(m, c, w1, b1), aval_c1(m, c+1, w1, b1));
    return;
  }
  idx -= 12800;
  if (idx < 3328) {
    int q = idx & 3, lane = (idx >> 2) & 31, mt = (idx >> 7) & 1, kt = idx >> 8;
    int m = mt*16 + (lane >> 2) + ((q & 1) << 3);
    int c = kt*16 + ((lane & 3) << 1) + ((q >> 1) << 3);
    g_afrag2[idx] = pk2bf(aval_rd(m, c, wr, br), aval_rd(m, c+1, wr, br));
    return;
  }
  idx -= 3328;
  if (idx < 4608) {
    int q = idx & 3, lane = (idx >> 2) & 31, mt = (idx >> 7) & 1, kt = idx >> 8;
    int m = mt*16 + (lane >> 2) + ((q & 1) << 3);
    int c = kt*16 + ((lane & 3) << 1) + ((q >> 1) << 3);
    g_afrag3[idx] = pk2bf(aval_ps(m, c, wp1, false), aval_ps(m, c+1, wp1, false));
    return;
  }
  idx -= 4608;
  if (idx < 4608) {
    int q = idx & 3, lane = (idx >> 2) & 31, mt = (idx >> 7) & 1, kt = idx >> 8;
    int m = mt*16 + (lane >> 2) + ((q & 1) << 3);
    int c = kt*16 + ((lane & 3) << 1) + ((q >> 1) << 3);
    g_afrag4[idx] = pk2bf(aval_ps(m, c, wp1, true), aval_ps(m, c+1, wp1, true));
  }
}

// ---------------------------------------------------------------------------
// K1 (HMMA, R11 passing version): half-row (64 px).
// ---------------------------------------------------------------------------
#define PB1 72
#define FS_OFF 0
#define B1F_OFF 8704
#define SMF_BYTES 66304

__global__ __launch_bounds__(256, 3) void k_front_mma(
    const float* __restrict__ x, const float* __restrict__ a1p,
    float* __restrict__ dummy)
{
  extern __shared__ char smf[];
  const int t = threadIdx.x;
  const int wid = t >> 5, lane = t & 31;
  const int h  = blockIdx.x;
  const int p0 = blockIdx.y * 64;
  const int b  = blockIdx.z;
  const float a1 = *a1p;
  float* fs = (float*)(smf + FS_OFF);
  __nv_bfloat16* B = (__nv_bfloat16*)(smf + B1F_OFF);
  const uint32_t Bbase = smem_u32(smf) + B1F_OFF;

  {
    const float* xb = x + (b*128)*HWc + h*Wc + p0;
    for (int i = t; i < 4096; i += 256) {
      int c = i >> 5, n2 = (i & 31) * 2;
      float2 xv = *(const float2*)&xb[c*HWc + n2];
      __nv_bfloat16 h0, l0, h1, l1; bf_split(xv.x, h0, l0); bf_split(xv.y, h1, l1);
      uint32_t hh = pk2bf(h0, h1), ll = pk2bf(l0, l1);
      *(uint32_t*)&B[c*PB1 + n2]         = hh;
      *(uint32_t*)&B[(128 + c)*PB1 + n2] = hh;
      *(uint32_t*)&B[(256 + c)*PB1 + n2] = ll;
    }
    __nv_bfloat16 one = __float2bfloat16(1.0f);
    uint32_t oo = pk2bf(one, one);
    for (int i = t; i < 512; i += 256) {
      int r = 384 + (i >> 5), n2 = (i & 31) * 2;
      *(uint32_t*)&B[r*PB1 + n2] = (r < 386) ? oo : 0u;
    }
  }
  __syncthreads();

  const int mw = wid & 3, nw = wid >> 2;
  const uint4* __restrict__ afp1 = (const uint4*)g_afrag1;
  float d[4][4];
  #pragma unroll
  for (int nt = 0; nt < 4; nt++)
    #pragma unroll
    for (int q = 0; q < 4; q++) d[nt][q] = 0.f;

  uint4 a0 = afp1[(0*4 + mw)*32 + lane];
  #pragma unroll 1
  for (int kt = 0; kt < 25; kt++) {
    uint4 na;
    if (kt < 24) na = afp1[((kt+1)*4 + mw)*32 + lane];
    const uint32_t brow = Bbase + (uint32_t)(((kt*16 + (lane & 15))*PB1 + nw*32) * 2);
    #pragma unroll
    for (int nt = 0; nt < 4; nt++) {
      uint32_t bf[2];
      ldsm2t(bf, brow + nt*16);
      mma_bf16(d[nt], (const uint32_t*)&a0, bf);
    }
    a0 = na;
  }
  __syncthreads();

  {
    const int r = lane >> 2, c2 = (lane & 3) * 2;
    float* gx1b = g_x1 + (b*64)*HWc + h*Wc + p0;
    #pragma unroll
    for (int nt = 0; nt < 4; nt++) {
      const int n = nw*32 + nt*8 + c2;
      #pragma unroll
      for (int half = 0; half < 2; half++) {
        const int m = mw*16 + r + half*8;
        float v0 = d[nt][half*2], v1 = d[nt][half*2 + 1];
        v0 = (v0 >= 0.f) ? v0 : a1*v0;
        v1 = (v1 >= 0.f) ? v1 : a1*v1;
        *(float2*)&gx1b[m*HWc + n] = make_float2(v0, v1);
        __nv_bfloat16 h0, l0, h1, l1; bf_split(v0, h0, l0); bf_split(v1, h1, l1);
        uint32_t hh = pk2bf(h0, h1), ll = pk2bf(l0, l1);
        *(uint32_t*)&B[m*PB1 + n]         = hh;
        *(uint32_t*)&B[(64 + m)*PB1 + n]  = hh;
        *(uint32_t*)&B[(128 + m)*PB1 + n] = ll;
      }
    }
    __nv_bfloat16 one = __float2bfloat16(1.0f);
    uint32_t oo = pk2bf(one, one);
    for (int i = t; i < 512; i += 256) {
      int rr = 192 + (i >> 5), n2 = (i & 31) * 2;
      *(uint32_t*)&B[rr*PB1 + n2] = (rr < 194) ? oo : 0u;
    }
  }
  __syncthreads();

  const int mw2 = wid & 1, nw2 = wid >> 1;
  const uint4* __restrict__ afp2 = (const uint4*)g_afrag2;
  float d2[2][4];
  #pragma unroll
  for (int nt = 0; nt < 2; nt++)
    #pragma unroll
    for (int q = 0; q < 4; q++) d2[nt][q] = 0.f;

  uint4 a2 = afp2[(0*2 + mw2)*32 + lane];
  #pragma unroll 1
  for (int kt = 0; kt < 13; kt++) {
    uint4 na;
    if (kt < 12) na = afp2[((kt+1)*2 + mw2)*32 + lane];
    const uint32_t brow = Bbase + (uint32_t)(((kt*16 + (lane & 15))*PB1 + nw2*16) * 2);
    #pragma unroll
    for (int nt = 0; nt < 2; nt++) {
      uint32_t bf[2];
      ldsm2t(bf, brow + nt*16);
      mma_bf16(d2[nt], (const uint32_t*)&a2, bf);
    }
    a2 = na;
  }

  {
    const int r = lane >> 2, c2 = (lane & 3) * 2;
    float* gfb = g_f + (b*32)*HWc + h*Wc + p0;
    #pragma unroll
    for (int nt = 0; nt < 2; nt++) {
      const int n = nw2*16 + nt*8 + c2;
      #pragma unroll
      for (int half = 0; half < 2; half++) {
        const int m = mw2*16 + r + half*8;
        float v0 = fmaxf(d2[nt][half*2], 0.f);
        float v1 = fmaxf(d2[nt][half*2 + 1], 0.f);
        *(float2*)&gfb[m*HWc + n] = make_float2(v0, v1);
        *(float2*)&fs[m*68 + n]   = make_float2(v0, v1);
      }
    }
  }
  __syncthreads();

  if (t < 64) {
    float mx = -1e30f, sum = 0.f;
    #pragma unroll
    for (int c = 0; c < 32; c++) {
      float v = fs[c*68 + t];
      mx = fmaxf(mx, v);
      sum += v;
    }
    g_zp[(b*2)*HWc + h*Wc + p0 + t]   = mx;
    g_zp[(b*2+1)*HWc + h*Wc + p0 + t] = sum * (1.f/32.f);
  }
}

// ---------------------------------------------------------------------------
// K2: involution, ch-paired x1 layout (R12/R13 passing version). Tile 32x2.
// ---------------------------------------------------------------------------
__global__ __launch_bounds__(256, 2) void k_inv(
    const float* __restrict__ ws, const float* __restrict__ bs,
    const float* __restrict__ a2p)
{
  extern __shared__ float sm[];
  float* x1h = sm;                // 32 chp * 304 pix * 2 = 19456
  float* wss = x1h + 19456;       // 6272
  float* bss = wss + 6272;        // 196
  float* fts = bss + 196;         // 64*33
  const int t = threadIdx.x;
  const int w0 = blockIdx.x << 5;
  const int h0 = blockIdx.y << 1;
  const int b  = blockIdx.z;
  const float a2 = *a2p;

  const float* gx1b = g_x1 + (b*64)*HWc;
  for (int i = t; i < 19456; i += 256) {
    int ch = i / 304, r = i - ch*304;
    int yy = r / 38, xx = r - yy*38;
    int gh = h0 - 3 + yy, gw = w0 - 3 + xx;
    float v = 0.f;
    if ((unsigned)gh < 128u && (unsigned)gw < 128u)
      v = gx1b[ch*HWc + gh*Wc + gw];
    x1h[(ch >> 1)*608 + r*2 + (ch & 1)] = v;
  }
  for (int i = t; i < 6272; i += 256) wss[i] = ws[i];
  if (t < 196) bss[t] = bs[t];
  const float* gfb = g_f + (b*32)*HWc;
  for (int i = t; i < 2048; i += 256) {
    int c = i >> 6, p = i & 63;
    fts[p*33 + c] = gfb[c*HWc + (h0 + (p>>5))*Wc + w0 + (p&31)];
  }
  __syncthreads();

  const int p = t & 63, j = t >> 6;
  const int py = p >> 5, px = p & 31;

  u64p fp[16];
  #pragma unroll
  for (int c2 = 0; c2 < 16; c2++)
    fp[c2] = pk(fts[p*33 + 2*c2], fts[p*33 + 2*c2 + 1]);

  u64p acc2[8];
  #pragma unroll
  for (int chp = 0; chp < 8; chp++) acc2[chp] = 0ull;

  const float* wb = wss + j*49*32;
  const float* bb = bss + j*49;
  const float* xb = x1h + (j*8)*608 + (py*38 + px)*2;

  #pragma unroll 1
  for (int dy = 0; dy < 7; dy++) {
    #pragma unroll 1
    for (int dx = 0; dx < 7; dx++) {
      const int tt = dy*7 + dx;
      const float* wr2 = wb + tt*32;
      u64p k0 = 0ull, k1 = 0ull;
      #pragma unroll
      for (int c4 = 0; c4 < 8; c4++) {
        float4 wv = *(const float4*)&wr2[c4*4];
        fma2(k0, pk(wv.x, wv.y), fp[2*c4]);
        fma2(k1, pk(wv.z, wv.w), fp[2*c4 + 1]);
      }
      float2 ka = up(k0), kb = up(k1);
      const float kwt = bb[tt] + ((ka.x + ka.y) + (kb.x + kb.y));
      const u64p kd = pk(kwt, kwt);
      const float* src = xb + (dy*38 + dx)*2;
      #pragma unroll
      for (int chp = 0; chp < 8; chp++) {
        u64p v = *(const u64p*)&src[chp*608];
        fma2(acc2[chp], kd, v);
      }
    }
  }

  float* gx2b = g_x2 + (b*64 + j*16)*HWc + (h0 + py)*Wc + (w0 + px);
  #pragma unroll
  for (int chp = 0; chp < 8; chp++) {
    float2 v = up(acc2[chp]);
    float e = (v.x >= 0.f) ? v.x : a2*v.x;
    float o = (v.y >= 0.f) ? v.y : a2*v.y;
    gx2b[(2*chp)*HWc]     = e;
    gx2b[(2*chp + 1)*HWc] = o;
  }
}

// ---------------------------------------------------------------------------
// K3 (HMMA): psec 3x3 conv as im2col GEMM. CTA = one image row (128 px).
// D[32 oc][128 px], K'=288 (dj,di,ci). 3 accumulating passes.
// NEW build: shift-aware writes — 1 float2 LDG serves all 3 dj rows; no
// integer division; unique-column STS (pad col 128/129 absorbs overflow).
// ---------------------------------------------------------------------------
#define PBP 136
#define SMP_BYTES (288*PBP*2)   // 78336

__global__ __launch_bounds__(256, 2) void k_psec_mma(
    const float* __restrict__ bp1, const float* __restrict__ app)
{
  extern __shared__ char smp[];
  __nv_bfloat16* B = (__nv_bfloat16*)smp;
  const uint32_t Bbase = smem_u32(smp);
  const int t = threadIdx.x;
  const int wid = t >> 5, lane = t & 31;
  const int h = blockIdx.x;
  const int b = blockIdx.y;
  const float ap = *app;
  const float* gfb = g_f + (b*32)*HWc;
  const __nv_bfloat16 z16 = __float2bfloat16(0.f);

  const int mw = wid & 1;        // 2 m-tiles (32 oc)
  const int nw = wid >> 1;       // 4 n-quarters (32 px each)

  float d[4][4];
  #pragma unroll
  for (int nt = 0; nt < 4; nt++)
    #pragma unroll
    for (int q = 0; q < 4; q++) d[nt][q] = 0.f;

  // ---- build B = xhi (one LDG.64 serves dj=0,1,2 rows) ----
  if (t < 192) {
    if (t < 96) B[t*PBP] = z16;                // dj=0, col 0  (= f[-1])
    else        B[(96 + t)*PBP + 127] = z16;   // dj=2 rows 192..287, col 127 (= f[128])
  }
  for (int i = t; i < 96*64; i += 256) {
    int row96 = i >> 6;                        // di*32 + ci
    int n2 = (i & 63) * 2;
    int di = row96 >> 5, ci = row96 & 31;
    int gh = h + di - 1;
    float v0 = 0.f, v1 = 0.f;
    if ((unsigned)gh < 128u) {
      float2 fv = *(const float2*)&gfb[ci*HWc + gh*Wc + n2];
      v0 = fv.x; v1 = fv.y;
    }
    __nv_bfloat16 h0 = __float2bfloat16(v0), h1 = __float2bfloat16(v1);
    *(uint32_t*)&B[(96 + row96)*PBP + n2] = pk2bf(h0, h1);   // dj=1 aligned
    __nv_bfloat16* r0 = &B[row96*PBP];                       // dj=0: f[col-1]
    r0[n2 + 1] = h0; r0[n2 + 2] = h1;                        // col 128 = pad
    __nv_bfloat16* r2 = &B[(192 + row96)*PBP];               // dj=2: f[col+1]
    if (n2 > 0) r2[n2 - 1] = h0;
    r2[n2] = h1;
  }
  __syncthreads();

  // pass 1: Whi * xhi ; pass 2: Wlo * xhi
  #pragma unroll 1
  for (int pass = 0; pass < 2; pass++) {
    const uint4* __restrict__ afp = (const uint4*)(pass == 0 ? g_afrag3 : g_afrag4);
    uint4 a0 = afp[(0*2 + mw)*32 + lane];
    #pragma unroll 1
    for (int kt = 0; kt < 18; kt++) {
      uint4 na;
      if (kt < 17) na = afp[((kt+1)*2 + mw)*32 + lane];
      const uint32_t brow = Bbase + (uint32_t)(((kt*16 + (lane & 15))*PBP + nw*32) * 2);
      #pragma unroll
      for (int nt = 0; nt < 4; nt++) {
        uint32_t bf[2];
        ldsm2t(bf, brow + nt*16);
        mma_bf16(d[nt], (const uint32_t*)&a0, bf);
      }
      a0 = na;
    }
  }
  __syncthreads();

  // ---- build B = xlo (same structure) ----
  if (t < 192) {
    if (t < 96) B[t*PBP] = z16;
    else        B[(96 + t)*PBP + 127] = z16;
  }
  for (int i = t; i < 96*64; i += 256) {
    int row96 = i >> 6;
    int n2 = (i & 63) * 2;
    int di = row96 >> 5, ci = row96 & 31;
    int gh = h + di - 1;
    float v0 = 0.f, v1 = 0.f;
    if ((unsigned)gh < 128u) {
      float2 fv = *(const float2*)&gfb[ci*HWc + gh*Wc + n2];
      v0 = fv.x; v1 = fv.y;
    }
    __nv_bfloat16 h0, l0, h1, l1; bf_split(v0, h0, l0); bf_split(v1, h1, l1);
    *(uint32_t*)&B[(96 + row96)*PBP + n2] = pk2bf(l0, l1);
    __nv_bfloat16* r0 = &B[row96*PBP];
    r0[n2 + 1] = l0; r0[n2 + 2] = l1;
    __nv_bfloat16* r2 = &B[(192 + row96)*PBP];
    if (n2 > 0) r2[n2 - 1] = l0;
    r2[n2] = l1;
  }
  __syncthreads();

  // pass 3: Whi * xlo
  {
    const uint4* __restrict__ afp = (const uint4*)g_afrag3;
    uint4 a0 = afp[(0*2 + mw)*32 + lane];
    #pragma unroll 1
    for (int kt = 0; kt < 18; kt++) {
      uint4 na;
      if (kt < 17) na = afp[((kt+1)*2 + mw)*32 + lane];
      const uint32_t brow = Bbase + (uint32_t)(((kt*16 + (lane & 15))*PBP + nw*32) * 2);
      #pragma unroll
      for (int nt = 0; nt < 4; nt++) {
        uint32_t bf[2];
        ldsm2t(bf, brow + nt*16);
        mma_bf16(d[nt], (const uint32_t*)&a0, bf);
      }
      a0 = na;
    }
  }

  // ---- epilogue: +bias, PReLU -> g_h ----
  {
    const int r = lane >> 2, c2 = (lane & 3) * 2;
    float* ghb = g_h + (b*32)*HWc + h*Wc;
    #pragma unroll
    for (int half = 0; half < 2; half++) {
      const int m = mw*16 + r + half*8;
      const float bv = bp1[m];
      #pragma unroll
      for (int nt = 0; nt < 4; nt++) {
        const int n = nw*32 + nt*8 + c2;
        float v0 = d[nt][half*2]     + bv;
        float v1 = d[nt][half*2 + 1] + bv;
        v0 = (v0 >= 0.f) ? v0 : ap*v0;
        v1 = (v1 >= 0.f) ? v1 : ap*v1;
        *(float2*)&ghb[m*HWc + n] = make_float2(v0, v1);
      }
    }
  }
}

// ---------------------------------------------------------------------------
// K4: HMMA final (R10/R11 passing version).
// ---------------------------------------------------------------------------
#define PB 136
#define B_OFF 8448
#define SM4_BYTES (B_OFF + 304*PB*2)   // 91136

__global__ __launch_bounds__(256, 2) void k_final_mma(
    const float* __restrict__ wa, const float* __restrict__ ba,
    float* __restrict__ out)
{
  extern __shared__ char sm4[];
  const int t = threadIdx.x;
  const int wid = t >> 5, lane = t & 31;
  const int h = blockIdx.x & 127;
  const int b = blockIdx.x >> 7;
  float* attns = (float*)(sm4);
  float* was   = (float*)(sm4 + 512);
  float* zph   = (float*)(sm4 + 912);
  __nv_bfloat16* B = (__nv_bfloat16*)(sm4 + B_OFF);
  const uint32_t sbase = smem_u32(sm4);

  {
    const float* gzb = g_zp + (b*2)*HWc;
    for (int i = t; i < 1876; i += 256) {
      int c = i / 938, r = i - c*938;
      int yy = r / 134, xx = r - yy*134;
      int gh = h - 3 + yy, gw = xx - 3;
      float v = 0.f;
      if ((unsigned)gh < 128u && (unsigned)gw < 128u)
        v = gzb[c*HWc + gh*Wc + gw];
      zph[i] = v;
    }
    if (t < 98) was[t] = wa[t];
  }
  __syncthreads();

  if (t < 128) {
    float aacc = *ba;
    #pragma unroll
    for (int dy = 0; dy < 7; dy++)
      #pragma unroll
      for (int dx = 0; dx < 7; dx++) {
        const int o1 = dy*134 + t + dx;
        aacc += was[dy*7+dx]*zph[o1] + was[49 + dy*7+dx]*zph[938 + o1];
      }
    attns[t] = 1.f / (1.f + expf(-aacc));
  }
  __syncthreads();

  {
    const float* gx2b = g_x2 + (b*64)*HWc + h*Wc;
    for (int i = t; i < 4096; i += 256) {
      int c = i >> 6, n2 = (i & 63) * 2;
      float2 xv = *(const float2*)&gx2b[c*HWc + n2];
      float y0 = xv.x * attns[n2], y1 = xv.y * attns[n2+1];
      __nv_bfloat16 h0, l0, h1, l1; bf_split(y0, h0, l0); bf_split(y1, h1, l1);
      uint32_t hh = pk2bf(h0, h1), ll = pk2bf(l0, l1);
      *(uint32_t*)&B[c*PB + n2]         = hh;
      *(uint32_t*)&B[(64 + c)*PB + n2]  = hh;
      *(uint32_t*)&B[(128 + c)*PB + n2] = ll;
    }
    const float* ghb = g_h + (b*32)*HWc + h*Wc;
    for (int i = t; i < 2048; i += 256) {
      int c = i >> 6, n2 = (i & 63) * 2;
      float2 hv = *(const float2*)&ghb[c*HWc + n2];
      __nv_bfloat16 h0, l0, h1, l1; bf_split(hv.x, h0, l0); bf_split(hv.y, h1, l1);
      uint32_t hh = pk2bf(h0, h1), ll = pk2bf(l0, l1);
      *(uint32_t*)&B[(192 + c)*PB + n2] = hh;
      *(uint32_t*)&B[(224 + c)*PB + n2] = hh;
      *(uint32_t*)&B[(256 + c)*PB + n2] = ll;
    }
    if (t < 64) {
      int n2 = t*2;
      __nv_bfloat16 h0, l0, h1, l1;
      bf_split(attns[n2], h0, l0); bf_split(attns[n2+1], h1, l1);
      uint32_t hh = pk2bf(h0, h1), ll = pk2bf(l0, l1);
      *(uint32_t*)&B[288*PB + n2] = hh;
      *(uint32_t*)&B[289*PB + n2] = hh;
      *(uint32_t*)&B[290*PB + n2] = ll;
      __nv_bfloat16 one = __float2bfloat16(1.0f);
      uint32_t oo = pk2bf(one, one);
      *(uint32_t*)&B[291*PB + n2] = oo;
      *(uint32_t*)&B[292*PB + n2] = oo;
    }
    for (int i = t; i < 11*64; i += 256) {
      int r = 293 + (i >> 6), n2 = (i & 63) * 2;
      *(uint32_t*)&B[r*PB + n2] = 0u;
    }
  }
  __syncthreads();

  const int mw = wid & 3, nw = wid >> 2;
  const uint32_t Bbase = sbase + B_OFF;
  const uint4* __restrict__ afp = (const uint4*)g_afrag;

  float d[2][8][4];
  #pragma unroll
  for (int mt = 0; mt < 2; mt++)
    #pragma unroll
    for (int nt = 0; nt < 8; nt++)
      #pragma unroll
      for (int q = 0; q < 4; q++) d[mt][nt][q] = 0.f;

  uint4 a0 = afp[(0*8 + mw*2 + 0)*32 + lane];
  uint4 a1 = afp[(0*8 + mw*2 + 1)*32 + lane];

  #pragma unroll 1
  for (int kt = 0; kt < 19; kt++) {
    uint4 na0, na1;
    if (kt < 18) {
      na0 = afp[((kt+1)*8 + mw*2 + 0)*32 + lane];
      na1 = afp[((kt+1)*8 + mw*2 + 1)*32 + lane];
    }
    const uint32_t brow = Bbase + (uint32_t)(((kt*16 + (lane & 15))*PB + nw*64) * 2);
    #pragma unroll
    for (int nt = 0; nt < 8; nt++) {
      uint32_t bf[2];
      ldsm2t(bf, brow + nt*16);
      mma_bf16(d[0][nt], (const uint32_t*)&a0, bf);
      mma_bf16(d[1][nt], (const uint32_t*)&a1, bf);
    }
    a0 = na0; a1 = na1;
  }

  const int r = lane >> 2, c2 = (lane & 3) * 2;
  const int m_base = mw*32, n_base = nw*64;
  float* ob = out + (b*128)*HWc + h*Wc;
  #pragma unroll
  for (int mt = 0; mt < 2; mt++) {
    #pragma unroll
    for (int nt = 0; nt < 8; nt++) {
      const int m = m_base + mt*16 + r;
      const int n = n_base + nt*8 + c2;
      *(float2*)&ob[m*HWc + n]       = make_float2(d[mt][nt][0], d[mt][nt][1]);
      *(float2*)&ob[(m + 8)*HWc + n] = make_float2(d[mt][nt][2], d[mt][nt][3]);
    }
  }
}

// ---------------------------------------------------------------------------
extern "C" void kernel_launch(void* const* d_in, const int* in_sizes, int n_in,
                              void* d_out, int out_size)
{
  const float* x   = (const float*)d_in[0];
  const float* w1  = (const float*)d_in[1];
  const float* b1  = (const float*)d_in[2];
  const float* a1  = (const float*)d_in[3];
  const float* wr  = (const float*)d_in[4];
  const float* br  = (const float*)d_in[5];
  const float* ws  = (const float*)d_in[6];
  const float* bs  = (const float*)d_in[7];
  const float* a2  = (const float*)d_in[8];
  const float* w2  = (const float*)d_in[9];
  const float* b2  = (const float*)d_in[10];
  const float* wa  = (const float*)d_in[11];
  const float* ba  = (const float*)d_in[12];
  const float* wp1 = (const float*)d_in[13];
  const float* bp1 = (const float*)d_in[14];
  const float* ap  = (const float*)d_in[15];
  const float* wp2 = (const float*)d_in[16];
  const float* bp2 = (const float*)d_in[17];
  float* out = (float*)d_out;

  const int s2 = 28036 * 4;   // k_inv

  cudaFuncSetAttribute(k_front_mma, cudaFuncAttributeMaxDynamicSharedMemorySize, SMF_BYTES);
  cudaFuncSetAttribute(k_inv,       cudaFuncAttributeMaxDynamicSharedMemorySize, s2);
  cudaFuncSetAttribute(k_psec_mma,  cudaFuncAttributeMaxDynamicSharedMemorySize, SMP_BYTES);
  cudaFuncSetAttribute(k_final_mma, cudaFuncAttributeMaxDynamicSharedMemorySize, SM4_BYTES);

  k_prep_afrag<<<175, 256>>>(w2, b2, wp2, bp2, w1, b1, wr, br, wp1);
  k_front_mma<<<dim3(128, 2, 2), 256, SMF_BYTES>>>(x, a1, out);
  k_inv  <<<dim3(4, 64, 2), 256, s2>>>(ws, bs, a2);
  k_psec_mma<<<dim3(128, 2), 256, SMP_BYTES>>>(bp1, ap);
  k_final_mma<<<256, 256, SM4_BYTES>>>(wa, ba, out);
}